// round 3
// baseline (speedup 1.0000x reference)
#include <cuda_runtime.h>
#include <cuda_bf16.h>

// Fused soft-VQ: out = softmax(-soft_rate * ||x - C||) @ C
// Flash-attention style single pass over the codebook (online softmax),
// SIMT fp32 baseline. N=32768, K=8192, D=256 (derived from in_sizes).

#define BM 64          // x rows per block
#define BN 64          // codebook entries per tile
#define DD 256         // feature dim
#define XS_STRIDE 260  // padded float stride for x/c tiles (bank-conflict avoidance)
#define SS_STRIDE 65   // padded stride for score tile

// shared layout (floats)
#define OFF_XS 0
#define OFF_CS (OFF_XS + BM * XS_STRIDE)           // 16640
#define OFF_SS (OFF_CS + BN * XS_STRIDE)           // 33280
#define OFF_X2 (OFF_SS + BM * SS_STRIDE)           // 37440
#define OFF_C2 (OFF_X2 + BM)
#define OFF_M  (OFF_C2 + BN)
#define OFF_L  (OFF_M + BM)
#define OFF_A  (OFF_L + BM)
#define SMEM_FLOATS (OFF_A + BM)                   // 37760
#define SMEM_BYTES (SMEM_FLOATS * 4)               // 151040

__global__ __launch_bounds__(256, 1)
void vq_soft_kernel(const float* __restrict__ x,
                    const float* __restrict__ cbk,
                    float* __restrict__ out,
                    int Ktot)
{
    extern __shared__ float sm[];
    float* xs   = sm + OFF_XS;
    float* cs   = sm + OFF_CS;
    float* ss   = sm + OFF_SS;
    float* x2   = sm + OFF_X2;
    float* c2   = sm + OFF_C2;
    float* mrow = sm + OFF_M;
    float* lrow = sm + OFF_L;
    float* arow = sm + OFF_A;

    const int tid  = threadIdx.x;
    const int row0 = blockIdx.x * BM;

    // ---- load x tile [BM, D] (float4, coalesced) ----
    for (int e = tid; e < BM * DD / 4; e += 256) {
        int r  = e >> 6;          // 64 float4 per row
        int c4 = e & 63;
        float4 v = ((const float4*)(x + (long long)(row0 + r) * DD))[c4];
        float* dst = xs + r * XS_STRIDE + c4 * 4;
        dst[0] = v.x; dst[1] = v.y; dst[2] = v.z; dst[3] = v.w;
    }
    __syncthreads();

    // ---- row norms + softmax state init ----
    if (tid < BM) {
        float s = 0.f;
        const float* xr = xs + tid * XS_STRIDE;
        #pragma unroll 8
        for (int k = 0; k < DD; k++) s += xr[k] * xr[k];
        x2[tid]   = s;
        mrow[tid] = -1e30f;
        lrow[tid] = 0.f;
    }

    // ---- O accumulator: thread (rg,cg) owns rows 4*rg..+3, cols 16*cg..+15 ----
    const int tr = tid >> 4, tc = tid & 15;   // S-GEMM mapping (4x4 tile)
    const int rg = tid >> 4, cg = tid & 15;   // O-GEMM mapping (4x16 tile)
    const int si = tid >> 2, sq4 = tid & 3;   // softmax mapping (row si, quarter)

    float o[4][16];
    #pragma unroll
    for (int r = 0; r < 4; r++)
        #pragma unroll
        for (int c = 0; c < 16; c++) o[r][c] = 0.f;

    const int nTiles = Ktot / BN;
    for (int kt = 0; kt < nTiles; kt++) {
        __syncthreads();   // protects cs/ss reuse from previous iteration

        // ---- load codebook tile [BN, D] ----
        const int col0 = kt * BN;
        for (int e = tid; e < BN * DD / 4; e += 256) {
            int r  = e >> 6;
            int c4 = e & 63;
            float4 v = ((const float4*)(cbk + (long long)(col0 + r) * DD))[c4];
            float* dst = cs + r * XS_STRIDE + c4 * 4;
            dst[0] = v.x; dst[1] = v.y; dst[2] = v.z; dst[3] = v.w;
        }
        __syncthreads();

        if (tid < BN) {
            float s = 0.f;
            const float* cr = cs + tid * XS_STRIDE;
            #pragma unroll 8
            for (int k = 0; k < DD; k++) s += cr[k] * cr[k];
            c2[tid] = s;
        }
        __syncthreads();

        // ---- S = x . c  (4x4 register tile per thread) ----
        float acc[4][4];
        #pragma unroll
        for (int a = 0; a < 4; a++)
            #pragma unroll
            for (int b = 0; b < 4; b++) acc[a][b] = 0.f;

        const float* xb  = xs + (4 * tr) * XS_STRIDE;
        const float* cb2 = cs + (4 * tc) * XS_STRIDE;
        #pragma unroll 4
        for (int k = 0; k < DD; k += 4) {
            float4 xv[4], cv[4];
            #pragma unroll
            for (int a = 0; a < 4; a++) xv[a] = *(const float4*)(xb + a * XS_STRIDE + k);
            #pragma unroll
            for (int b = 0; b < 4; b++) cv[b] = *(const float4*)(cb2 + b * XS_STRIDE + k);
            #pragma unroll
            for (int a = 0; a < 4; a++)
                #pragma unroll
                for (int b = 0; b < 4; b++)
                    acc[a][b] += xv[a].x * cv[b].x + xv[a].y * cv[b].y
                               + xv[a].z * cv[b].z + xv[a].w * cv[b].w;
        }

        // ---- epilogue: logits = -10 * sqrt(max(x2 + c2 - 2 dot, 0)) ----
        #pragma unroll
        for (int a = 0; a < 4; a++) {
            float xx = x2[4 * tr + a];
            #pragma unroll
            for (int b = 0; b < 4; b++) {
                float sqv = xx + c2[4 * tc + b] - 2.f * acc[a][b];
                sqv = fmaxf(sqv, 0.f);
                ss[(4 * tr + a) * SS_STRIDE + (4 * tc + b)] = -10.f * sqrtf(sqv);
            }
        }
        __syncthreads();

        // ---- online softmax update (4 threads per row, 16 cols each) ----
        {
            float* srw = ss + si * SS_STRIDE + sq4 * 16;
            float tmax = -1e30f;
            #pragma unroll
            for (int j = 0; j < 16; j++) tmax = fmaxf(tmax, srw[j]);
            tmax = fmaxf(tmax, __shfl_xor_sync(0xffffffffu, tmax, 1));
            tmax = fmaxf(tmax, __shfl_xor_sync(0xffffffffu, tmax, 2));
            const float mold = mrow[si];
            const float newm = fmaxf(mold, tmax);
            float psum = 0.f;
            #pragma unroll
            for (int j = 0; j < 16; j++) {
                float p = __expf(srw[j] - newm);
                srw[j] = p;
                psum += p;
            }
            psum += __shfl_xor_sync(0xffffffffu, psum, 1);
            psum += __shfl_xor_sync(0xffffffffu, psum, 2);
            if (sq4 == 0) {
                float alpha = __expf(mold - newm);
                lrow[si] = lrow[si] * alpha + psum;
                mrow[si] = newm;
                arow[si] = alpha;
            }
        }
        __syncthreads();

        // ---- O = O*alpha + P @ C_tile  (4 rows x 16 cols per thread) ----
        {
            float al[4];
            #pragma unroll
            for (int r = 0; r < 4; r++) al[r] = arow[4 * rg + r];
            #pragma unroll
            for (int r = 0; r < 4; r++)
                #pragma unroll
                for (int c = 0; c < 16; c++) o[r][c] *= al[r];

            #pragma unroll 4
            for (int j = 0; j < BN; j++) {
                float p[4];
                #pragma unroll
                for (int r = 0; r < 4; r++) p[r] = ss[(4 * rg + r) * SS_STRIDE + j];
                const float* crow = cs + j * XS_STRIDE + cg * 16;
                float cvv[16];
                #pragma unroll
                for (int c = 0; c < 16; c += 4) {
                    float4 v = *(const float4*)(crow + c);
                    cvv[c] = v.x; cvv[c + 1] = v.y; cvv[c + 2] = v.z; cvv[c + 3] = v.w;
                }
                #pragma unroll
                for (int r = 0; r < 4; r++)
                    #pragma unroll
                    for (int c = 0; c < 16; c++)
                        o[r][c] += p[r] * cvv[c];
            }
        }
    }
    __syncthreads();

    // ---- finalize: out = O / l ----
    #pragma unroll
    for (int r = 0; r < 4; r++) {
        float inv = 1.f / lrow[4 * rg + r];
        float* orow = out + (long long)(row0 + 4 * rg + r) * DD + cg * 16;
        #pragma unroll
        for (int c = 0; c < 16; c += 4) {
            float4 v;
            v.x = o[r][c] * inv;
            v.y = o[r][c + 1] * inv;
            v.z = o[r][c + 2] * inv;
            v.w = o[r][c + 3] * inv;
            *(float4*)(orow + c) = v;
        }
    }
}

// Fill possible tail of d_out (the reference's second tuple element, -1)
__global__ void fill_tail_kernel(float* p, long long n)
{
    long long i = (long long)blockIdx.x * blockDim.x + threadIdx.x;
    if (i < n) p[i] = -1.0f;
}

extern "C" void kernel_launch(void* const* d_in, const int* in_sizes, int n_in,
                              void* d_out, int out_size)
{
    const float* x   = (const float*)d_in[0];
    const float* cbk = (const float*)d_in[1];
    float* out = (float*)d_out;

    const int N = in_sizes[0] / DD;   // 32768
    const int K = in_sizes[1] / DD;   // 8192

    cudaFuncSetAttribute(vq_soft_kernel,
                         cudaFuncAttributeMaxDynamicSharedMemorySize, SMEM_BYTES);

    dim3 grid(N / BM);
    vq_soft_kernel<<<grid, 256, SMEM_BYTES>>>(x, cbk, out, K);

    long long nd = (long long)N * DD;
    if ((long long)out_size > nd) {
        long long tail = (long long)out_size - nd;
        int thr = 256;
        int blocks = (int)((tail + thr - 1) / thr);
        fill_tail_kernel<<<blocks, thr>>>(out + nd, tail);
    }
}

// round 5
// speedup vs baseline: 8.0564x; 8.0564x over previous
#include <cuda_runtime.h>
#include <cuda_bf16.h>
#include <cstdint>

// Fused soft-VQ on tensor cores (tf32 mma.sync, flash-style, fixed-ref softmax)
// out = softmax(-10 * ||x - C||) @ C ; N=32768, K=8192, D=256

#define DD  256
#define BM  128
#define BN  64
#define XS_STRIDE 260   // pad: stride % 32 == 4 -> ldmatrix conflict-free
#define CS_STRIDE 260
#define PS_STRIDE 36    // 32 + 4

#define NMAX 32768
#define KMAX 8192

// smem float offsets
#define OFF_XS 0
#define OFF_CS (OFF_XS + BM * XS_STRIDE)            // 33280
#define OFF_PS (OFF_CS + BN * CS_STRIDE)            // 49920
#define OFF_LB (OFF_PS + BM * PS_STRIDE)            // 54528
#define SMEM_FLOATS (OFF_LB + 2 * BM)               // 54784
#define SMEM_BYTES (SMEM_FLOATS * 4)                // 219136

#define LOG2E10 14.4269504088896f   // 10 * log2(e)

__device__ float g_x2[NMAX];
__device__ float g_c2[KMAX];

// ---------------- helpers ----------------
__device__ __forceinline__ uint32_t cvt_rna_tf32(float v) {
    uint32_t u;
    asm("cvt.rna.tf32.f32 %0, %1;" : "=r"(u) : "f"(v));
    return u;
}
__device__ __forceinline__ float sqrt_approx(float v) {
    float r;
    asm("sqrt.approx.f32 %0, %1;" : "=f"(r) : "f"(v));
    return r;
}
__device__ __forceinline__ float ex2_approx(float v) {
    float r;
    asm("ex2.approx.f32 %0, %1;" : "=f"(r) : "f"(v));
    return r;
}
__device__ __forceinline__ void ldm_x4(uint32_t addr, uint32_t& r0, uint32_t& r1,
                                       uint32_t& r2, uint32_t& r3) {
    asm volatile("ldmatrix.sync.aligned.m8n8.x4.shared.b16 {%0,%1,%2,%3}, [%4];"
                 : "=r"(r0), "=r"(r1), "=r"(r2), "=r"(r3) : "r"(addr));
}
__device__ __forceinline__ void mma_tf32(float* d, const uint32_t* a,
                                         uint32_t b0, uint32_t b1) {
    asm volatile(
        "mma.sync.aligned.m16n8k8.row.col.f32.tf32.tf32.f32 "
        "{%0,%1,%2,%3}, {%4,%5,%6,%7}, {%8,%9}, {%0,%1,%2,%3};"
        : "+f"(d[0]), "+f"(d[1]), "+f"(d[2]), "+f"(d[3])
        : "r"(a[0]), "r"(a[1]), "r"(a[2]), "r"(a[3]), "r"(b0), "r"(b1));
}

// ---------------- prep: row norms of x and C ----------------
__global__ void prep_norms(const float* __restrict__ x,
                           const float* __restrict__ cbk, int N, int K) {
    int w    = (blockIdx.x * blockDim.x + threadIdx.x) >> 5;
    int lane = threadIdx.x & 31;
    if (w >= N + K) return;
    const float* src;
    float* dst;
    if (w < N) { src = x + (long long)w * DD;       dst = g_x2 + w; }
    else       { src = cbk + (long long)(w - N) * DD; dst = g_c2 + (w - N); }
    float s = 0.f;
    #pragma unroll
    for (int i = lane; i < DD / 4; i += 32) {
        float4 v = ((const float4*)src)[i];
        s += v.x * v.x + v.y * v.y + v.z * v.z + v.w * v.w;
    }
    #pragma unroll
    for (int d = 16; d > 0; d >>= 1) s += __shfl_xor_sync(0xffffffffu, s, d);
    if (lane == 0) *dst = s;
}

// ---------------- main fused kernel ----------------
__global__ __launch_bounds__(256, 1)
void vq_tc_kernel(const float* __restrict__ x,
                  const float* __restrict__ cbk,
                  float* __restrict__ out, int Ktot)
{
    extern __shared__ float sm[];
    float* xs = sm + OFF_XS;
    float* cs = sm + OFF_CS;
    float* ps = sm + OFF_PS;
    float* lb = sm + OFF_LB;

    const int tid  = threadIdx.x;
    const int w    = tid >> 5;
    const int lane = tid & 31;
    const int wm   = w >> 1;       // 0..3 : S row-block 32*wm
    const int wn   = w & 1;        // 0..1 : S col-block 32*wn
    const int q    = lane >> 2;    // quad row
    const int m    = lane & 3;     // quad col
    const long long row0 = (long long)blockIdx.x * BM;

    const uint32_t xs_b = (uint32_t)__cvta_generic_to_shared(xs);
    const uint32_t cs_b = (uint32_t)__cvta_generic_to_shared(cs);
    const uint32_t ps_b = (uint32_t)__cvta_generic_to_shared(ps);

    // ---- stage x tile [128][256] (cvt.rna to tf32 bits) ----
    for (int e = tid; e < BM * DD / 4; e += 256) {
        int r = e >> 6, c4 = e & 63;
        float4 v = ((const float4*)(x + (row0 + r) * DD))[c4];
        uint4 u;
        u.x = cvt_rna_tf32(v.x); u.y = cvt_rna_tf32(v.y);
        u.z = cvt_rna_tf32(v.z); u.w = cvt_rna_tf32(v.w);
        *(uint4*)(xs + r * XS_STRIDE + c4 * 4) = u;
    }
    __syncthreads();

    // ---- per-thread row constants (S rows) ----
    float x2s[2][2], m2s[2][2];
    #pragma unroll
    for (int mt = 0; mt < 2; mt++)
        #pragma unroll
        for (int h = 0; h < 2; h++) {
            int rr = 32 * wm + 16 * mt + q + 8 * h;
            float xx = g_x2[row0 + rr];
            x2s[mt][h] = xx;
            m2s[mt][h] = LOG2E10 * sqrt_approx(xx);
        }

    float o[32][4];
    #pragma unroll
    for (int nt = 0; nt < 32; nt++)
        #pragma unroll
        for (int c = 0; c < 4; c++) o[nt][c] = 0.f;
    float lsum[2][2] = {{0.f, 0.f}, {0.f, 0.f}};

    // ldmatrix lane address components
    const int lrow = lane & 15;               // row within 16
    const int lkof = (lane & 16) >> 2;        // +4 f32 cols for upper half

    const int nTiles = Ktot / BN;
    for (int kt = 0; kt < nTiles; kt++) {
        const int col0 = kt * BN;

        // ---- stage C tile [64][256] ----
        for (int e = tid; e < BN * DD / 4; e += 256) {
            int r = e >> 6, c4 = e & 63;
            float4 v = ((const float4*)(cbk + (long long)(col0 + r) * DD))[c4];
            uint4 u;
            u.x = cvt_rna_tf32(v.x); u.y = cvt_rna_tf32(v.y);
            u.z = cvt_rna_tf32(v.z); u.w = cvt_rna_tf32(v.w);
            *(uint4*)(cs + r * CS_STRIDE + c4 * 4) = u;
        }
        __syncthreads();

        // c2 for this thread's S columns
        float2 c2v[4];
        #pragma unroll
        for (int nf = 0; nf < 4; nf++)
            c2v[nf] = *(const float2*)&g_c2[col0 + 32 * wn + 8 * nf + 2 * m];

        // ---- MMA1: S[32wm..+31][32wn..+31] ----
        float sfr[2][4][4];
        #pragma unroll
        for (int mt = 0; mt < 2; mt++)
            #pragma unroll
            for (int nf = 0; nf < 4; nf++)
                #pragma unroll
                for (int c = 0; c < 4; c++) sfr[mt][nf][c] = 0.f;

        #pragma unroll 8
        for (int kk = 0; kk < 32; kk++) {
            const int k0 = kk * 8;
            uint32_t a[2][4];
            #pragma unroll
            for (int mt = 0; mt < 2; mt++) {
                uint32_t ad = xs_b +
                    ((32 * wm + 16 * mt + lrow) * XS_STRIDE + k0 + lkof) * 4;
                ldm_x4(ad, a[mt][0], a[mt][1], a[mt][2], a[mt][3]);
            }
            uint32_t bfr[4][2];
            #pragma unroll
            for (int bp = 0; bp < 2; bp++) {
                uint32_t r0, r1, r2, r3;
                uint32_t ad = cs_b +
                    ((32 * wn + 16 * bp + lrow) * CS_STRIDE + k0 + lkof) * 4;
                ldm_x4(ad, r0, r1, r2, r3);
                bfr[2 * bp][0] = r0; bfr[2 * bp][1] = r2;      // nf = 2bp
                bfr[2 * bp + 1][0] = r1; bfr[2 * bp + 1][1] = r3; // nf = 2bp+1
            }
            #pragma unroll
            for (int mt = 0; mt < 2; mt++)
                #pragma unroll
                for (int nf = 0; nf < 4; nf++)
                    mma_tf32(sfr[mt][nf], a[mt], bfr[nf][0], bfr[nf][1]);
        }

        // ---- epilogue: p = exp2(m2 - 10*log2e*sqrt(max(x2+c2-2s,0))) ----
        #pragma unroll
        for (int mt = 0; mt < 2; mt++)
            #pragma unroll
            for (int nf = 0; nf < 4; nf++)
                #pragma unroll
                for (int h = 0; h < 2; h++) {
                    float s0 = sfr[mt][nf][2 * h];
                    float s1 = sfr[mt][nf][2 * h + 1];
                    float sq0 = fmaf(-2.f, s0, x2s[mt][h]) + c2v[nf].x;
                    float sq1 = fmaf(-2.f, s1, x2s[mt][h]) + c2v[nf].y;
                    float r0 = sqrt_approx(fmaxf(sq0, 0.f));
                    float r1 = sqrt_approx(fmaxf(sq1, 0.f));
                    float p0 = ex2_approx(fmaf(-LOG2E10, r0, m2s[mt][h]));
                    float p1 = ex2_approx(fmaf(-LOG2E10, r1, m2s[mt][h]));
                    lsum[mt][h] += p0 + p1;
                    sfr[mt][nf][2 * h]     = __uint_as_float(cvt_rna_tf32(p0));
                    sfr[mt][nf][2 * h + 1] = __uint_as_float(cvt_rna_tf32(p1));
                }

        // ---- MMA2 in two j-half passes through the P buffer ----
        #pragma unroll
        for (int pass = 0; pass < 2; pass++) {
            if (wn == pass) {
                #pragma unroll
                for (int mt = 0; mt < 2; mt++)
                    #pragma unroll
                    for (int nf = 0; nf < 4; nf++) {
                        int rr = 32 * wm + 16 * mt + q;
                        int cc = 8 * nf + 2 * m;
                        *(float2*)&ps[rr * PS_STRIDE + cc] =
                            make_float2(sfr[mt][nf][0], sfr[mt][nf][1]);
                        *(float2*)&ps[(rr + 8) * PS_STRIDE + cc] =
                            make_float2(sfr[mt][nf][2], sfr[mt][nf][3]);
                    }
            }
            __syncthreads();

            const int jbase = pass * 32;
            #pragma unroll
            for (int kf = 0; kf < 4; kf++) {
                uint32_t pa[4];
                uint32_t ad = ps_b +
                    ((16 * w + lrow) * PS_STRIDE + kf * 8 + lkof) * 4;
                ldm_x4(ad, pa[0], pa[1], pa[2], pa[3]);
                const float* crow0 = cs + (jbase + kf * 8 + m) * CS_STRIDE;
                const float* crow1 = crow0 + 4 * CS_STRIDE;
                #pragma unroll
                for (int nt = 0; nt < 32; nt++) {
                    uint32_t b0 = __float_as_uint(crow0[nt * 8 + q]);
                    uint32_t b1 = __float_as_uint(crow1[nt * 8 + q]);
                    mma_tf32(o[nt], pa, b0, b1);
                }
            }
            __syncthreads();   // protect ps (next pass) / cs (next tile)
        }
    }

    // ---- combine row sums across wn halves ----
    #pragma unroll
    for (int mt = 0; mt < 2; mt++)
        #pragma unroll
        for (int h = 0; h < 2; h++) {
            float v = lsum[mt][h];
            v += __shfl_xor_sync(0xffffffffu, v, 1);
            v += __shfl_xor_sync(0xffffffffu, v, 2);
            if (m == 0)
                lb[wn * BM + 32 * wm + 16 * mt + q + 8 * h] = v;
        }
    __syncthreads();

    float inv0, inv1;
    {
        int r = 16 * w + q;
        inv0 = 1.f / (lb[r] + lb[BM + r]);
        inv1 = 1.f / (lb[r + 8] + lb[BM + r + 8]);
    }
    #pragma unroll
    for (int nt = 0; nt < 32; nt++) {
        int r = 16 * w + q;
        float* p0 = out + (row0 + r) * DD + nt * 8 + 2 * m;
        float* p1 = out + (row0 + r + 8) * DD + nt * 8 + 2 * m;
        *(float2*)p0 = make_float2(o[nt][0] * inv0, o[nt][1] * inv0);
        *(float2*)p1 = make_float2(o[nt][2] * inv1, o[nt][3] * inv1);
    }
}

// Fill possible tail of d_out (the reference's second tuple element, -1)
__global__ void fill_tail_kernel(float* p, long long n)
{
    long long i = (long long)blockIdx.x * blockDim.x + threadIdx.x;
    if (i < n) p[i] = -1.0f;
}

extern "C" void kernel_launch(void* const* d_in, const int* in_sizes, int n_in,
                              void* d_out, int out_size)
{
    const float* x   = (const float*)d_in[0];
    const float* cbk = (const float*)d_in[1];
    float* out = (float*)d_out;

    const int N = in_sizes[0] / DD;   // 32768
    const int K = in_sizes[1] / DD;   // 8192

    // prep: row norms
    {
        int warps = N + K;
        int thr = 256;
        int blocks = (warps * 32 + thr - 1) / thr;
        prep_norms<<<blocks, thr>>>(x, cbk, N, K);
    }

    cudaFuncSetAttribute(vq_tc_kernel,
                         cudaFuncAttributeMaxDynamicSharedMemorySize, SMEM_BYTES);
    vq_tc_kernel<<<N / BM, 256, SMEM_BYTES>>>(x, cbk, out, K);

    long long nd = (long long)N * DD;
    if ((long long)out_size > nd) {
        long long tail = (long long)out_size - nd;
        int thr = 256;
        int blocks = (int)((tail + thr - 1) / thr);
        fill_tail_kernel<<<blocks, thr>>>(out + nd, tail);
    }
}

// round 7
// speedup vs baseline: 9.8868x; 1.2272x over previous
#include <cuda_runtime.h>
#include <cuda_bf16.h>
#include <cstdint>

// Fused soft-VQ, tf32 mma.sync, transposed-operand formulation:
//   MMA1: S^T = C * X^T   (A-frags: cs natural, B-frags: xs natural)
//   MMA2: O^T = C^T * P^T (B-frags: ps natural ldmatrix, A-frags: 64 scalar LDS)
// out = softmax(-10 * ||x - C||) @ C ; N=32768, K=8192, D=256

#define DD  256
#define BM  128
#define BN  64
#define XS_STRIDE 260   // 65 quads (odd) -> ldmatrix conflict-free
#define CS_STRIDE 260
#define PS_STRIDE 36    // 9 quads (odd)

#define NMAX 32768
#define KMAX 8192

// smem float offsets
#define OFF_XS 0
#define OFF_CS (OFF_XS + BM * XS_STRIDE)            // 33280
#define OFF_PS (OFF_CS + BN * CS_STRIDE)            // 49920
#define OFF_LB (OFF_PS + BM * PS_STRIDE)            // 54528
#define SMEM_FLOATS (OFF_LB + 2 * BM)               // 54784
#define SMEM_BYTES (SMEM_FLOATS * 4)                // 219136

#define LOG2E10 14.4269504088896f   // 10 * log2(e)

__device__ float g_x2[NMAX];
__device__ float g_c2[KMAX];

// ---------------- helpers ----------------
__device__ __forceinline__ uint32_t cvt_rna_tf32(float v) {
    uint32_t u;
    asm("cvt.rna.tf32.f32 %0, %1;" : "=r"(u) : "f"(v));
    return u;
}
__device__ __forceinline__ float sqrt_approx(float v) {
    float r;
    asm("sqrt.approx.f32 %0, %1;" : "=f"(r) : "f"(v));
    return r;
}
__device__ __forceinline__ float ex2_approx(float v) {
    float r;
    asm("ex2.approx.f32 %0, %1;" : "=f"(r) : "f"(v));
    return r;
}
__device__ __forceinline__ void ldm_x4(uint32_t addr, uint32_t& r0, uint32_t& r1,
                                       uint32_t& r2, uint32_t& r3) {
    asm volatile("ldmatrix.sync.aligned.m8n8.x4.shared.b16 {%0,%1,%2,%3}, [%4];"
                 : "=r"(r0), "=r"(r1), "=r"(r2), "=r"(r3) : "r"(addr));
}
__device__ __forceinline__ void mma_tf32(float* d, const uint32_t* a,
                                         uint32_t b0, uint32_t b1) {
    asm volatile(
        "mma.sync.aligned.m16n8k8.row.col.f32.tf32.tf32.f32 "
        "{%0,%1,%2,%3}, {%4,%5,%6,%7}, {%8,%9}, {%0,%1,%2,%3};"
        : "+f"(d[0]), "+f"(d[1]), "+f"(d[2]), "+f"(d[3])
        : "r"(a[0]), "r"(a[1]), "r"(a[2]), "r"(a[3]), "r"(b0), "r"(b1));
}

// ---------------- prep: row norms of x and C ----------------
__global__ void prep_norms(const float* __restrict__ x,
                           const float* __restrict__ cbk, int N, int K) {
    int w    = (blockIdx.x * blockDim.x + threadIdx.x) >> 5;
    int lane = threadIdx.x & 31;
    if (w >= N + K) return;
    const float* src;
    float* dst;
    if (w < N) { src = x + (long long)w * DD;         dst = g_x2 + w; }
    else       { src = cbk + (long long)(w - N) * DD; dst = g_c2 + (w - N); }
    float s = 0.f;
    #pragma unroll
    for (int i = lane; i < DD / 4; i += 32) {
        float4 v = ((const float4*)src)[i];
        s += v.x * v.x + v.y * v.y + v.z * v.z + v.w * v.w;
    }
    #pragma unroll
    for (int d = 16; d > 0; d >>= 1) s += __shfl_xor_sync(0xffffffffu, s, d);
    if (lane == 0) *dst = s;
}

// ---------------- main fused kernel ----------------
__global__ __launch_bounds__(256, 1)
void vq_tc_kernel(const float* __restrict__ x,
                  const float* __restrict__ cbk,
                  float* __restrict__ out, int Ktot)
{
    extern __shared__ float sm[];
    float* xs = sm + OFF_XS;
    float* cs = sm + OFF_CS;
    float* ps = sm + OFF_PS;
    float* lb = sm + OFF_LB;

    const int tid  = threadIdx.x;
    const int w    = tid >> 5;
    const int lane = tid & 31;
    const int wm   = w >> 2;       // 0..1 : S^T j-half  (32 j per warp)
    const int wn   = w & 3;        // 0..3 : S^T r-quarter (32 r per warp)
    const int q    = lane >> 2;    // 0..7
    const int m    = lane & 3;     // 0..3
    const long long row0 = (long long)blockIdx.x * BM;

    const uint32_t xs_b = (uint32_t)__cvta_generic_to_shared(xs);
    const uint32_t cs_b = (uint32_t)__cvta_generic_to_shared(cs);
    const uint32_t ps_b = (uint32_t)__cvta_generic_to_shared(ps);

    // ldmatrix 16-row addressing components
    const int lrow = lane & 15;
    const int lkof = (lane & 16) >> 2;   // +4 f32 cols for upper 16 lanes

    // ---- stage x tile [128][256] (tf32 bits) ----
    for (int e = tid; e < BM * DD / 4; e += 256) {
        int r = e >> 6, c4 = e & 63;
        float4 v = ((const float4*)(x + (row0 + r) * DD))[c4];
        uint4 u;
        u.x = cvt_rna_tf32(v.x); u.y = cvt_rna_tf32(v.y);
        u.z = cvt_rna_tf32(v.z); u.w = cvt_rna_tf32(v.w);
        *(uint4*)(xs + r * XS_STRIDE + c4 * 4) = u;
    }

    // ---- per-lane r constants (this warp's r-range: 32*wn .. +31) ----
    float x2v[4][2], m2v[4][2];
    #pragma unroll
    for (int nf = 0; nf < 4; nf++)
        #pragma unroll
        for (int par = 0; par < 2; par++) {
            int r = 32 * wn + 8 * nf + 2 * m + par;
            float xx = g_x2[row0 + r];
            x2v[nf][par] = xx;
            m2v[nf][par] = LOG2E10 * sqrt_approx(xx);
        }

    // O^T accumulators: warp owns d-range 32*w..+31 (2 mtiles), all 128 r (16 ntiles)
    float o[2][16][4];
    #pragma unroll
    for (int mtd = 0; mtd < 2; mtd++)
        #pragma unroll
        for (int nt = 0; nt < 16; nt++)
            #pragma unroll
            for (int c = 0; c < 4; c++) o[mtd][nt][c] = 0.f;
    float lsum[4][2] = {{0.f,0.f},{0.f,0.f},{0.f,0.f},{0.f,0.f}};

    const int nTiles = Ktot / BN;
    for (int kt = 0; kt < nTiles; kt++) {
        const int col0 = kt * BN;

        // ---- stage C tile [64][256] (tf32 bits) ----
        for (int e = tid; e < BN * DD / 4; e += 256) {
            int r = e >> 6, c4 = e & 63;
            float4 v = ((const float4*)(cbk + (long long)(col0 + r) * DD))[c4];
            uint4 u;
            u.x = cvt_rna_tf32(v.x); u.y = cvt_rna_tf32(v.y);
            u.z = cvt_rna_tf32(v.z); u.w = cvt_rna_tf32(v.w);
            *(uint4*)(cs + r * CS_STRIDE + c4 * 4) = u;
        }

        // c2 for this lane's j positions (warp j-range 32*wm..+31)
        float c2v[2][2];
        #pragma unroll
        for (int mt = 0; mt < 2; mt++)
            #pragma unroll
            for (int h = 0; h < 2; h++)
                c2v[mt][h] = g_c2[col0 + 32 * wm + 16 * mt + q + 8 * h];

        __syncthreads();   // cs staged (also orders xs on iter 0)

        // ---- MMA1: S^T[32j x 32r] = C * X^T ----
        float sfr[2][4][4];
        #pragma unroll
        for (int mt = 0; mt < 2; mt++)
            #pragma unroll
            for (int nf = 0; nf < 4; nf++)
                #pragma unroll
                for (int c = 0; c < 4; c++) sfr[mt][nf][c] = 0.f;

        #pragma unroll 8
        for (int kk = 0; kk < 32; kk++) {
            const int k0 = kk * 8;
            uint32_t a[2][4];
            #pragma unroll
            for (int mt = 0; mt < 2; mt++) {
                uint32_t ad = cs_b +
                    ((32 * wm + 16 * mt + lrow) * CS_STRIDE + k0 + lkof) * 4;
                ldm_x4(ad, a[mt][0], a[mt][1], a[mt][2], a[mt][3]);
            }
            uint32_t bfr[4][2];
            #pragma unroll
            for (int bp = 0; bp < 2; bp++) {
                uint32_t r0, r1, r2, r3;
                uint32_t ad = xs_b +
                    ((32 * wn + 16 * bp + lrow) * XS_STRIDE + k0 + lkof) * 4;
                ldm_x4(ad, r0, r1, r2, r3);
                bfr[2 * bp][0] = r0;     bfr[2 * bp][1] = r2;
                bfr[2 * bp + 1][0] = r1; bfr[2 * bp + 1][1] = r3;
            }
            #pragma unroll
            for (int mt = 0; mt < 2; mt++)
                #pragma unroll
                for (int nf = 0; nf < 4; nf++)
                    mma_tf32(sfr[mt][nf], a[mt], bfr[nf][0], bfr[nf][1]);
        }

        // ---- epilogue on S^T frags: p = exp2(m2[r] - L*sqrt(x2[r]+c2[j]-2s)) ----
        #pragma unroll
        for (int mt = 0; mt < 2; mt++)
            #pragma unroll
            for (int nf = 0; nf < 4; nf++) {
                float s0 = sfr[mt][nf][0];   // (j0+q,   rA)
                float s1 = sfr[mt][nf][1];   // (j0+q,   rA+1)
                float s2 = sfr[mt][nf][2];   // (j0+q+8, rA)
                float s3 = sfr[mt][nf][3];   // (j0+q+8, rA+1)
                float sq0 = fmaf(-2.f, s0, x2v[nf][0]) + c2v[mt][0];
                float sq1 = fmaf(-2.f, s1, x2v[nf][1]) + c2v[mt][0];
                float sq2 = fmaf(-2.f, s2, x2v[nf][0]) + c2v[mt][1];
                float sq3 = fmaf(-2.f, s3, x2v[nf][1]) + c2v[mt][1];
                float r0 = sqrt_approx(fmaxf(sq0, 0.f));
                float r1 = sqrt_approx(fmaxf(sq1, 0.f));
                float r2 = sqrt_approx(fmaxf(sq2, 0.f));
                float r3 = sqrt_approx(fmaxf(sq3, 0.f));
                float p0 = ex2_approx(fmaf(-LOG2E10, r0, m2v[nf][0]));
                float p1 = ex2_approx(fmaf(-LOG2E10, r1, m2v[nf][1]));
                float p2 = ex2_approx(fmaf(-LOG2E10, r2, m2v[nf][0]));
                float p3 = ex2_approx(fmaf(-LOG2E10, r3, m2v[nf][1]));
                lsum[nf][0] += p0 + p2;
                lsum[nf][1] += p1 + p3;
                sfr[mt][nf][0] = __uint_as_float(cvt_rna_tf32(p0));
                sfr[mt][nf][1] = __uint_as_float(cvt_rna_tf32(p1));
                sfr[mt][nf][2] = __uint_as_float(cvt_rna_tf32(p2));
                sfr[mt][nf][3] = __uint_as_float(cvt_rna_tf32(p3));
            }

        // ---- MMA2 in two j-half passes: O^T += C^T * P^T ----
        #pragma unroll
        for (int pass = 0; pass < 2; pass++) {
            if (wm == pass) {
                // store P (row-major [r][j_local]) — conflict-free scatter
                #pragma unroll
                for (int mt = 0; mt < 2; mt++)
                    #pragma unroll
                    for (int nf = 0; nf < 4; nf++) {
                        int jl = 16 * mt + q;
                        int rA = 32 * wn + 8 * nf + 2 * m;
                        ps[rA * PS_STRIDE + jl]           = sfr[mt][nf][0];
                        ps[(rA + 1) * PS_STRIDE + jl]     = sfr[mt][nf][1];
                        ps[rA * PS_STRIDE + jl + 8]       = sfr[mt][nf][2];
                        ps[(rA + 1) * PS_STRIDE + jl + 8] = sfr[mt][nf][3];
                    }
            }
            __syncthreads();

            #pragma unroll
            for (int jc = 0; jc < 4; jc++) {
                const int jg = 32 * pass + 8 * jc;   // global j for cs reads
                // A-frags (C^T): scalar LDS, reused over all 16 ntiles
                uint32_t a2[2][4];
                #pragma unroll
                for (int mtd = 0; mtd < 2; mtd++) {
                    const float* cp0 = cs + (jg + m) * CS_STRIDE + 32 * w + 16 * mtd;
                    const float* cp1 = cs + (jg + 4 + m) * CS_STRIDE + 32 * w + 16 * mtd;
                    a2[mtd][0] = __float_as_uint(cp0[q]);
                    a2[mtd][1] = __float_as_uint(cp0[q + 8]);
                    a2[mtd][2] = __float_as_uint(cp1[q]);
                    a2[mtd][3] = __float_as_uint(cp1[q + 8]);
                }
                // B-frags (P^T) via natural ldmatrix on ps
                uint32_t bb[16][2];
                #pragma unroll
                for (int g = 0; g < 8; g++) {
                    uint32_t r0, r1, r2, r3;
                    uint32_t ad = ps_b +
                        ((16 * g + lrow) * PS_STRIDE + 8 * jc + lkof) * 4;
                    ldm_x4(ad, r0, r1, r2, r3);
                    bb[2 * g][0] = r0;     bb[2 * g][1] = r2;
                    bb[2 * g + 1][0] = r1; bb[2 * g + 1][1] = r3;
                }
                #pragma unroll
                for (int mtd = 0; mtd < 2; mtd++)
                    #pragma unroll
                    for (int nt = 0; nt < 16; nt++)
                        mma_tf32(o[mtd][nt], a2[mtd], bb[nt][0], bb[nt][1]);
            }
            __syncthreads();   // pass0: before wm1 stores; pass1: before next cs/ps write
        }
    }

    // ---- reduce lsum over q-lanes (j direction), publish per (wm, r) ----
    #pragma unroll
    for (int nf = 0; nf < 4; nf++)
        #pragma unroll
        for (int par = 0; par < 2; par++) {
            float v = lsum[nf][par];
            v += __shfl_xor_sync(0xffffffffu, v, 4);
            v += __shfl_xor_sync(0xffffffffu, v, 8);
            v += __shfl_xor_sync(0xffffffffu, v, 16);
            if (q == 0)
                lb[wm * BM + 32 * wn + 8 * nf + 2 * m + par] = v;
        }
    __syncthreads();

    // ---- finalize: out[r][d] = O^T[d][r] / l[r] ----
    #pragma unroll
    for (int nt = 0; nt < 16; nt++) {
        int rA = 8 * nt + 2 * m;
        float invA = 1.f / (lb[rA] + lb[BM + rA]);
        float invB = 1.f / (lb[rA + 1] + lb[BM + rA + 1]);
        #pragma unroll
        for (int mtd = 0; mtd < 2; mtd++) {
            int d0 = 32 * w + 16 * mtd;
            float* oA = out + (row0 + rA) * DD + d0;
            float* oB = out + (row0 + rA + 1) * DD + d0;
            oA[q]     = o[mtd][nt][0] * invA;
            oB[q]     = o[mtd][nt][1] * invB;
            oA[q + 8] = o[mtd][nt][2] * invA;
            oB[q + 8] = o[mtd][nt][3] * invB;
        }
    }
}

// Fill possible tail of d_out (the reference's second tuple element, -1)
__global__ void fill_tail_kernel(float* p, long long n)
{
    long long i = (long long)blockIdx.x * blockDim.x + threadIdx.x;
    if (i < n) p[i] = -1.0f;
}

extern "C" void kernel_launch(void* const* d_in, const int* in_sizes, int n_in,
                              void* d_out, int out_size)
{
    const float* x   = (const float*)d_in[0];
    const float* cbk = (const float*)d_in[1];
    float* out = (float*)d_out;

    const int N = in_sizes[0] / DD;   // 32768
    const int K = in_sizes[1] / DD;   // 8192

    // prep: row norms
    {
        int warps = N + K;
        int thr = 256;
        int blocks = (warps * 32 + thr - 1) / thr;
        prep_norms<<<blocks, thr>>>(x, cbk, N, K);
    }

    cudaFuncSetAttribute(vq_tc_kernel,
                         cudaFuncAttributeMaxDynamicSharedMemorySize, SMEM_BYTES);
    vq_tc_kernel<<<N / BM, 256, SMEM_BYTES>>>(x, cbk, out, K);

    long long nd = (long long)N * DD;
    if ((long long)out_size > nd) {
        long long tail = (long long)out_size - nd;
        int thr = 256;
        int blocks = (int)((tail + thr - 1) / thr);
        fill_tail_kernel<<<blocks, thr>>>(out + nd, tail);
    }
}